// round 2
// baseline (speedup 1.0000x reference)
#include <cuda_runtime.h>

// Problem constants
constexpr int NB   = 128;   // batch
constexpr int NT   = 128;   // encoder time steps
constexpr int NIN  = 3;     // input features
constexpr int NH   = 512;   // hidden
constexpr int NTGT = 32;    // decoder steps

// ---------------------------------------------------------------------------
// Static device scratch (allocation-free rule: __device__ globals)
// ---------------------------------------------------------------------------
__device__ float g_l0[NT * NB * (2 * NH)];      // encoder L0 concat outputs [t][b][1024]  (67 MB)
__device__ float g_xs1[2 * NT * NB * NH];       // precomputed L1 input terms [d][t][b][512] (67 MB)
__device__ float g_h[2][2 * NB * NH];           // encoder recurrent state ping-pong [parity][dir][b][h]
__device__ float g_dech[2][4 * NB * NH];        // decoder state ping-pong [parity][layer][b][h]
__device__ float g_decin[2][NB * 4];            // decoder feedback input (padded to 4) [parity][b][i]

// ---------------------------------------------------------------------------
// Encoder layer 0 step: h = tanh(x_t @ Wih^T + bih + bhh + h_prev @ Whh^T)
// grid (16 j-tiles, 4 b-tiles, 2 dirs), 256 threads, tile 32b x 32j, 4 out/thread
// ---------------------------------------------------------------------------
__global__ void __launch_bounds__(256) enc0_step(
    const float* __restrict__ x, const float* __restrict__ Wih0,
    const float* __restrict__ Whh0, const float* __restrict__ bih,
    const float* __restrict__ bhh, int t)
{
    __shared__ __align__(16) float sh_h[32][36];
    __shared__ __align__(16) float sh_w[32][36];

    const int d  = blockIdx.z;
    const int td = d ? (NT - 1 - t) : t;
    const int j0 = blockIdx.x * 32;
    const int b0 = blockIdx.y * 32;
    const int tx = threadIdx.x & 7;      // j group (0..7), 4 j per thread
    const int ty = threadIdx.x >> 3;     // batch row (0..31)
    const int b  = b0 + ty;
    const int j  = j0 + tx * 4;

    const float* Whh   = Whh0 + d * NH * NH;
    const float* hprev = g_h[t & 1] + d * NB * NH;
    float*       hnext = g_h[(t + 1) & 1] + d * NB * NH;

    float a0, a1, a2, a3;
    {
        const float* xr = x + (b * NT + td) * NIN;
        const float  x0 = xr[0], x1 = xr[1], x2 = xr[2];
        const float* wi = Wih0 + (d * NH + j) * NIN;
        const float* bi = bih + d * NH + j;
        const float* bh = bhh + d * NH + j;
        a0 = bi[0] + bh[0] + x0 * wi[0] + x1 * wi[1]  + x2 * wi[2];
        a1 = bi[1] + bh[1] + x0 * wi[3] + x1 * wi[4]  + x2 * wi[5];
        a2 = bi[2] + bh[2] + x0 * wi[6] + x1 * wi[7]  + x2 * wi[8];
        a3 = bi[3] + bh[3] + x0 * wi[9] + x1 * wi[10] + x2 * wi[11];
    }

    if (t > 0) {
        const int lb = ty;           // 0..31
        const int lk = tx * 4;       // 0..28
        for (int k0 = 0; k0 < NH; k0 += 32) {
            *(float4*)&sh_h[lb][lk] = *(const float4*)&hprev[(b0 + lb) * NH + k0 + lk];
            float4 w = *(const float4*)&Whh[(j0 + lb) * NH + k0 + lk];
            sh_w[lk + 0][lb] = w.x; sh_w[lk + 1][lb] = w.y;
            sh_w[lk + 2][lb] = w.z; sh_w[lk + 3][lb] = w.w;
            __syncthreads();
#pragma unroll
            for (int kk = 0; kk < 32; kk++) {
                float  hv = sh_h[ty][kk];
                float4 wv = *(float4*)&sh_w[kk][tx * 4];
                a0 += hv * wv.x; a1 += hv * wv.y; a2 += hv * wv.z; a3 += hv * wv.w;
            }
            __syncthreads();
        }
    }

    float4 hv4 = make_float4(tanhf(a0), tanhf(a1), tanhf(a2), tanhf(a3));
    *(float4*)&hnext[b * NH + j] = hv4;
    *(float4*)&g_l0[(td * NB + b) * (2 * NH) + d * NH + j] = hv4;
    if (t == NT - 1)
        *(float4*)&g_dech[0][(d * NB + b) * NH + j] = hv4;   // hn slots 0 (fwd), 1 (bwd)
}

// ---------------------------------------------------------------------------
// Big GEMM: xs1[d][t][b][j] = l0[t][b][:] . Wih1[d][j][:] + bih1[d][j] + bhh1[d][j]
// M = 16384 (t,b), N = 512, K = 1024. Tile 64x64, 256 threads, 4x4 per thread.
// ---------------------------------------------------------------------------
__global__ void __launch_bounds__(256) xs1_gemm(
    const float* __restrict__ Wih1, const float* __restrict__ bih,
    const float* __restrict__ bhh)
{
    __shared__ __align__(16) float sh_a[64][36];
    __shared__ __align__(16) float sh_w[32][68];

    const int d  = blockIdx.z;
    const int j0 = blockIdx.x * 64;
    const int m0 = blockIdx.y * 64;
    const int tx = threadIdx.x & 15;     // j group (0..15), 4 j per thread
    const int ty = threadIdx.x >> 4;     // row group (0..15), 4 rows per thread
    const int lr = threadIdx.x >> 3;     // 0..31 (load row)
    const int lk = (threadIdx.x & 7) * 4;

    const float* Wd = Wih1 + d * NH * (2 * NH);
    float acc[4][4] = {};

    for (int k0 = 0; k0 < 2 * NH; k0 += 32) {
        *(float4*)&sh_a[lr][lk]      = *(const float4*)&g_l0[(m0 + lr) * (2 * NH) + k0 + lk];
        *(float4*)&sh_a[lr + 32][lk] = *(const float4*)&g_l0[(m0 + lr + 32) * (2 * NH) + k0 + lk];
        float4 w0 = *(const float4*)&Wd[(j0 + lr) * (2 * NH) + k0 + lk];
        float4 w1 = *(const float4*)&Wd[(j0 + lr + 32) * (2 * NH) + k0 + lk];
        sh_w[lk + 0][lr] = w0.x; sh_w[lk + 1][lr] = w0.y;
        sh_w[lk + 2][lr] = w0.z; sh_w[lk + 3][lr] = w0.w;
        sh_w[lk + 0][lr + 32] = w1.x; sh_w[lk + 1][lr + 32] = w1.y;
        sh_w[lk + 2][lr + 32] = w1.z; sh_w[lk + 3][lr + 32] = w1.w;
        __syncthreads();
#pragma unroll
        for (int kk = 0; kk < 32; kk++) {
            float4 wv = *(float4*)&sh_w[kk][tx * 4];
            float  v0 = sh_a[ty * 4 + 0][kk];
            float  v1 = sh_a[ty * 4 + 1][kk];
            float  v2 = sh_a[ty * 4 + 2][kk];
            float  v3 = sh_a[ty * 4 + 3][kk];
            acc[0][0] += v0 * wv.x; acc[0][1] += v0 * wv.y; acc[0][2] += v0 * wv.z; acc[0][3] += v0 * wv.w;
            acc[1][0] += v1 * wv.x; acc[1][1] += v1 * wv.y; acc[1][2] += v1 * wv.z; acc[1][3] += v1 * wv.w;
            acc[2][0] += v2 * wv.x; acc[2][1] += v2 * wv.y; acc[2][2] += v2 * wv.z; acc[2][3] += v2 * wv.w;
            acc[3][0] += v3 * wv.x; acc[3][1] += v3 * wv.y; acc[3][2] += v3 * wv.z; acc[3][3] += v3 * wv.w;
        }
        __syncthreads();
    }

    const int jj = j0 + tx * 4;
    const float b0v = bih[(2 + d) * NH + jj + 0] + bhh[(2 + d) * NH + jj + 0];
    const float b1v = bih[(2 + d) * NH + jj + 1] + bhh[(2 + d) * NH + jj + 1];
    const float b2v = bih[(2 + d) * NH + jj + 2] + bhh[(2 + d) * NH + jj + 2];
    const float b3v = bih[(2 + d) * NH + jj + 3] + bhh[(2 + d) * NH + jj + 3];
#pragma unroll
    for (int i = 0; i < 4; i++) {
        const int m = m0 + ty * 4 + i;
        float4 r = make_float4(acc[i][0] + b0v, acc[i][1] + b1v,
                               acc[i][2] + b2v, acc[i][3] + b3v);
        *(float4*)&g_xs1[(d * NT * NB + m) * NH + jj] = r;
    }
}

// ---------------------------------------------------------------------------
// Encoder layer 1 step: h = tanh(xs1[d][t] + h_prev @ Whh1[d]^T)
// ---------------------------------------------------------------------------
__global__ void __launch_bounds__(256) enc1_step(
    const float* __restrict__ Whh1, int t)
{
    __shared__ __align__(16) float sh_h[32][36];
    __shared__ __align__(16) float sh_w[32][36];

    const int d  = blockIdx.z;
    const int td = d ? (NT - 1 - t) : t;
    const int j0 = blockIdx.x * 32;
    const int b0 = blockIdx.y * 32;
    const int tx = threadIdx.x & 7;
    const int ty = threadIdx.x >> 3;
    const int b  = b0 + ty;
    const int j  = j0 + tx * 4;

    const float* Whh   = Whh1 + d * NH * NH;
    const float* hprev = g_h[t & 1] + d * NB * NH;
    float*       hnext = g_h[(t + 1) & 1] + d * NB * NH;

    float4 xt = *(const float4*)&g_xs1[((d * NT + td) * NB + b) * NH + j];
    float a0 = xt.x, a1 = xt.y, a2 = xt.z, a3 = xt.w;

    if (t > 0) {
        const int lb = ty, lk = tx * 4;
        for (int k0 = 0; k0 < NH; k0 += 32) {
            *(float4*)&sh_h[lb][lk] = *(const float4*)&hprev[(b0 + lb) * NH + k0 + lk];
            float4 w = *(const float4*)&Whh[(j0 + lb) * NH + k0 + lk];
            sh_w[lk + 0][lb] = w.x; sh_w[lk + 1][lb] = w.y;
            sh_w[lk + 2][lb] = w.z; sh_w[lk + 3][lb] = w.w;
            __syncthreads();
#pragma unroll
            for (int kk = 0; kk < 32; kk++) {
                float  hv = sh_h[ty][kk];
                float4 wv = *(float4*)&sh_w[kk][tx * 4];
                a0 += hv * wv.x; a1 += hv * wv.y; a2 += hv * wv.z; a3 += hv * wv.w;
            }
            __syncthreads();
        }
    }

    float4 hv4 = make_float4(tanhf(a0), tanhf(a1), tanhf(a2), tanhf(a3));
    *(float4*)&hnext[b * NH + j] = hv4;
    if (t == NT - 1)
        *(float4*)&g_dech[0][((2 + d) * NB + b) * NH + j] = hv4;  // hn slots 2 (fwd), 3 (bwd)
}

// ---------------------------------------------------------------------------
// Decoder: generic layer kernel. tile 16b x 32j, 128 threads, 4 out/thread.
// ---------------------------------------------------------------------------
__device__ __forceinline__ void gemm16x32(
    const float* __restrict__ V, const float* __restrict__ W,
    int b0, int j0, int tx, int ty,
    float& a0, float& a1, float& a2, float& a3,
    float (*sh_v)[36], float (*sh_w)[36])
{
    const int lb = threadIdx.x >> 3;        // 0..15
    const int lk = (threadIdx.x & 7) * 4;   // 0..28
    for (int k0 = 0; k0 < NH; k0 += 32) {
        *(float4*)&sh_v[lb][lk] = *(const float4*)&V[(b0 + lb) * NH + k0 + lk];
        float4 w0 = *(const float4*)&W[(j0 + lb) * NH + k0 + lk];
        float4 w1 = *(const float4*)&W[(j0 + lb + 16) * NH + k0 + lk];
        sh_w[lk + 0][lb] = w0.x; sh_w[lk + 1][lb] = w0.y;
        sh_w[lk + 2][lb] = w0.z; sh_w[lk + 3][lb] = w0.w;
        sh_w[lk + 0][lb + 16] = w1.x; sh_w[lk + 1][lb + 16] = w1.y;
        sh_w[lk + 2][lb + 16] = w1.z; sh_w[lk + 3][lb + 16] = w1.w;
        __syncthreads();
#pragma unroll
        for (int kk = 0; kk < 32; kk++) {
            float  hv = sh_v[ty][kk];
            float4 wv = *(float4*)&sh_w[kk][tx * 4];
            a0 += hv * wv.x; a1 += hv * wv.y; a2 += hv * wv.z; a3 += hv * wv.w;
        }
        __syncthreads();
    }
}

__global__ void __launch_bounds__(128) dec_layer(
    const float* __restrict__ x,   const float* __restrict__ Wih0,
    const float* __restrict__ Wihr, const float* __restrict__ Whh,
    const float* __restrict__ bih, const float* __restrict__ bhh,
    int t, int l)
{
    __shared__ __align__(16) float sh_v[16][36];
    __shared__ __align__(16) float sh_w[32][36];

    const int p  = t & 1;
    const int j0 = blockIdx.x * 32;
    const int b0 = blockIdx.y * 16;
    const int tx = threadIdx.x & 7;
    const int ty = threadIdx.x >> 3;    // 0..15
    const int b  = b0 + ty;
    const int j  = j0 + tx * 4;

    float a0 = bih[l * NH + j + 0] + bhh[l * NH + j + 0];
    float a1 = bih[l * NH + j + 1] + bhh[l * NH + j + 1];
    float a2 = bih[l * NH + j + 2] + bhh[l * NH + j + 2];
    float a3 = bih[l * NH + j + 3] + bhh[l * NH + j + 3];

    if (l == 0) {
        float i0, i1, i2;
        if (t == 0) {
            const float* xr = x + (b * NT + (NT - 1)) * NIN;
            i0 = xr[0]; i1 = xr[1]; i2 = xr[2];
        } else {
            const float* dr = g_decin[p] + b * 4;
            i0 = dr[0]; i1 = dr[1]; i2 = dr[2];
        }
        const float* wi = Wih0 + j * NIN;
        a0 += i0 * wi[0] + i1 * wi[1]  + i2 * wi[2];
        a1 += i0 * wi[3] + i1 * wi[4]  + i2 * wi[5];
        a2 += i0 * wi[6] + i1 * wi[7]  + i2 * wi[8];
        a3 += i0 * wi[9] + i1 * wi[10] + i2 * wi[11];
    }

    // recurrent term (t=0 reads hn written by the encoder)
    gemm16x32(g_dech[p] + l * NB * NH, Whh + l * NH * NH,
              b0, j0, tx, ty, a0, a1, a2, a3, sh_v, sh_w);
    // input term from layer below (written earlier this step)
    if (l > 0)
        gemm16x32(g_dech[1 - p] + (l - 1) * NB * NH, Wihr + (l - 1) * NH * NH,
                  b0, j0, tx, ty, a0, a1, a2, a3, sh_v, sh_w);

    float* hout = g_dech[1 - p] + l * NB * NH;
    float4 r = make_float4(tanhf(a0), tanhf(a1), tanhf(a2), tanhf(a3));
    *(float4*)&hout[b * NH + j] = r;
}

// ---------------------------------------------------------------------------
// Decoder output + feedback: out = h3 . linW + b;  nxt = [o0, x0-o0, x1-(x0-o0)]
// 32 blocks x 128 threads, one warp per batch row.
// ---------------------------------------------------------------------------
__global__ void __launch_bounds__(128) out_step(
    const float* __restrict__ x, const float* __restrict__ linW,
    const float* __restrict__ linb, float* __restrict__ out, int t)
{
    const int p    = t & 1;
    const int warp = threadIdx.x >> 5;
    const int lane = threadIdx.x & 31;
    const int b    = blockIdx.x * 4 + warp;

    const float* h3 = g_dech[1 - p] + 3 * NB * NH + b * NH;
    float s = 0.f;
#pragma unroll
    for (int j = lane; j < NH; j += 32) s += h3[j] * linW[j];
#pragma unroll
    for (int o = 16; o; o >>= 1) s += __shfl_xor_sync(0xffffffffu, s, o);

    if (lane == 0) {
        float o0 = s + linb[0];
        float xi0, xi1;
        if (t == 0) {
            const float* xr = x + (b * NT + (NT - 1)) * NIN;
            xi0 = xr[0]; xi1 = xr[1];
        } else {
            xi0 = g_decin[p][b * 4 + 0];
            xi1 = g_decin[p][b * 4 + 1];
        }
        float s1 = xi0 - o0;
        float s2 = xi1 - s1;
        g_decin[1 - p][b * 4 + 0] = o0;
        g_decin[1 - p][b * 4 + 1] = s1;
        g_decin[1 - p][b * 4 + 2] = s2;
        out[b * NTGT + t] = o0;
    }
}

// ---------------------------------------------------------------------------
// Launch sequence (graph-capturable: kernel launches only)
// ---------------------------------------------------------------------------
extern "C" void kernel_launch(void* const* d_in, const int* in_sizes, int n_in,
                              void* d_out, int out_size)
{
    const float* x        = (const float*)d_in[0];
    // d_in[1] = y (unused: teacher_forcing_ratio == 0)
    const float* enc_Wih0 = (const float*)d_in[2];
    const float* enc_Whh0 = (const float*)d_in[3];
    const float* enc_Wih1 = (const float*)d_in[4];
    const float* enc_Whh1 = (const float*)d_in[5];
    const float* enc_bih  = (const float*)d_in[6];
    const float* enc_bhh  = (const float*)d_in[7];
    const float* dec_Wih0 = (const float*)d_in[8];
    const float* dec_Wihr = (const float*)d_in[9];
    const float* dec_Whh  = (const float*)d_in[10];
    const float* dec_bih  = (const float*)d_in[11];
    const float* dec_bhh  = (const float*)d_in[12];
    const float* lin_W    = (const float*)d_in[13];
    const float* lin_b    = (const float*)d_in[14];
    float* out = (float*)d_out;

    const dim3 encGrid(16, 4, 2);   // j-tiles, b-tiles, dirs

    // Encoder layer 0 (fwd+bwd concurrently), writes l0 concat + hn[0..1]
    for (int t = 0; t < NT; t++)
        enc0_step<<<encGrid, 256>>>(x, enc_Wih0, enc_Whh0, enc_bih, enc_bhh, t);

    // Precompute layer-1 input terms for all t (both dirs), biases folded in
    xs1_gemm<<<dim3(8, 256, 2), 256>>>(enc_Wih1, enc_bih, enc_bhh);

    // Encoder layer 1 recurrence, writes hn[2..3]
    for (int t = 0; t < NT; t++)
        enc1_step<<<encGrid, 256>>>(enc_Whh1, t);

    // Decoder: 32 steps x (4 layers + output/feedback)
    for (int t = 0; t < NTGT; t++) {
        for (int l = 0; l < 4; l++)
            dec_layer<<<dim3(16, 8), 128>>>(x, dec_Wih0, dec_Wihr, dec_Whh,
                                            dec_bih, dec_bhh, t, l);
        out_step<<<32, 128>>>(x, lin_W, lin_b, out, t);
    }
}

// round 3
// speedup vs baseline: 1.0025x; 1.0025x over previous
#include <cuda_runtime.h>

// Problem constants
constexpr int NB   = 128;   // batch
constexpr int NT   = 128;   // encoder time steps
constexpr int NIN  = 3;     // input features
constexpr int NH   = 512;   // hidden
constexpr int NTGT = 32;    // decoder steps

// ---------------------------------------------------------------------------
// Static device scratch (allocation-free rule: __device__ globals)
// ---------------------------------------------------------------------------
__device__ float g_l0[NT * NB * (2 * NH)];      // encoder L0 concat outputs [t][b][1024]  (67 MB)
__device__ float g_xs1[2 * NT * NB * NH];       // precomputed L1 input terms [d][t][b][512] (67 MB)
__device__ float g_h[2][2 * NB * NH];           // encoder recurrent state ping-pong [parity][dir][b][h]
__device__ float g_dech[2][4 * NB * NH];        // decoder state ping-pong [parity][layer][b][h]
__device__ float g_decin[2][NB * 4];            // decoder feedback input (padded to 4) [parity][b][i]

// ---------------------------------------------------------------------------
// Encoder layer 0 step: h = tanh(x_t @ Wih^T + bih + bhh + h_prev @ Whh^T)
// grid (16 j-tiles, 4 b-tiles, 2 dirs), 256 threads, tile 32b x 32j, 4 out/thread
// ---------------------------------------------------------------------------
__global__ void __launch_bounds__(256) enc0_step(
    const float* __restrict__ x, const float* __restrict__ Wih0,
    const float* __restrict__ Whh0, const float* __restrict__ bih,
    const float* __restrict__ bhh, int t)
{
    __shared__ __align__(16) float sh_h[32][36];
    __shared__ __align__(16) float sh_w[32][36];

    const int d  = blockIdx.z;
    const int td = d ? (NT - 1 - t) : t;
    const int j0 = blockIdx.x * 32;
    const int b0 = blockIdx.y * 32;
    const int tx = threadIdx.x & 7;      // j group (0..7), 4 j per thread
    const int ty = threadIdx.x >> 3;     // batch row (0..31)
    const int b  = b0 + ty;
    const int j  = j0 + tx * 4;

    const float* Whh   = Whh0 + d * NH * NH;
    const float* hprev = g_h[t & 1] + d * NB * NH;
    float*       hnext = g_h[(t + 1) & 1] + d * NB * NH;

    float a0, a1, a2, a3;
    {
        const float* xr = x + (b * NT + td) * NIN;
        const float  x0 = xr[0], x1 = xr[1], x2 = xr[2];
        const float* wi = Wih0 + (d * NH + j) * NIN;
        const float* bi = bih + d * NH + j;
        const float* bh = bhh + d * NH + j;
        a0 = bi[0] + bh[0] + x0 * wi[0] + x1 * wi[1]  + x2 * wi[2];
        a1 = bi[1] + bh[1] + x0 * wi[3] + x1 * wi[4]  + x2 * wi[5];
        a2 = bi[2] + bh[2] + x0 * wi[6] + x1 * wi[7]  + x2 * wi[8];
        a3 = bi[3] + bh[3] + x0 * wi[9] + x1 * wi[10] + x2 * wi[11];
    }

    if (t > 0) {
        const int lb = ty;           // 0..31
        const int lk = tx * 4;       // 0..28
        for (int k0 = 0; k0 < NH; k0 += 32) {
            *(float4*)&sh_h[lb][lk] = *(const float4*)&hprev[(b0 + lb) * NH + k0 + lk];
            float4 w = *(const float4*)&Whh[(j0 + lb) * NH + k0 + lk];
            sh_w[lk + 0][lb] = w.x; sh_w[lk + 1][lb] = w.y;
            sh_w[lk + 2][lb] = w.z; sh_w[lk + 3][lb] = w.w;
            __syncthreads();
#pragma unroll
            for (int kk = 0; kk < 32; kk++) {
                float  hv = sh_h[ty][kk];
                float4 wv = *(float4*)&sh_w[kk][tx * 4];
                a0 += hv * wv.x; a1 += hv * wv.y; a2 += hv * wv.z; a3 += hv * wv.w;
            }
            __syncthreads();
        }
    }

    float4 hv4 = make_float4(tanhf(a0), tanhf(a1), tanhf(a2), tanhf(a3));
    *(float4*)&hnext[b * NH + j] = hv4;
    *(float4*)&g_l0[(td * NB + b) * (2 * NH) + d * NH + j] = hv4;
    if (t == NT - 1)
        *(float4*)&g_dech[0][(d * NB + b) * NH + j] = hv4;   // hn slots 0 (fwd), 1 (bwd)
}

// ---------------------------------------------------------------------------
// Big GEMM: xs1[d][t][b][j] = l0[t][b][:] . Wih1[d][j][:] + bih1[d][j] + bhh1[d][j]
// M = 16384 (t,b), N = 512, K = 1024. Tile 64x64, 256 threads, 4x4 per thread.
// ---------------------------------------------------------------------------
__global__ void __launch_bounds__(256) xs1_gemm(
    const float* __restrict__ Wih1, const float* __restrict__ bih,
    const float* __restrict__ bhh)
{
    __shared__ __align__(16) float sh_a[64][36];
    __shared__ __align__(16) float sh_w[32][68];

    const int d  = blockIdx.z;
    const int j0 = blockIdx.x * 64;
    const int m0 = blockIdx.y * 64;
    const int tx = threadIdx.x & 15;     // j group (0..15), 4 j per thread
    const int ty = threadIdx.x >> 4;     // row group (0..15), 4 rows per thread
    const int lr = threadIdx.x >> 3;     // 0..31 (load row)
    const int lk = (threadIdx.x & 7) * 4;

    const float* Wd = Wih1 + d * NH * (2 * NH);
    float acc[4][4] = {};

    for (int k0 = 0; k0 < 2 * NH; k0 += 32) {
        *(float4*)&sh_a[lr][lk]      = *(const float4*)&g_l0[(m0 + lr) * (2 * NH) + k0 + lk];
        *(float4*)&sh_a[lr + 32][lk] = *(const float4*)&g_l0[(m0 + lr + 32) * (2 * NH) + k0 + lk];
        float4 w0 = *(const float4*)&Wd[(j0 + lr) * (2 * NH) + k0 + lk];
        float4 w1 = *(const float4*)&Wd[(j0 + lr + 32) * (2 * NH) + k0 + lk];
        sh_w[lk + 0][lr] = w0.x; sh_w[lk + 1][lr] = w0.y;
        sh_w[lk + 2][lr] = w0.z; sh_w[lk + 3][lr] = w0.w;
        sh_w[lk + 0][lr + 32] = w1.x; sh_w[lk + 1][lr + 32] = w1.y;
        sh_w[lk + 2][lr + 32] = w1.z; sh_w[lk + 3][lr + 32] = w1.w;
        __syncthreads();
#pragma unroll
        for (int kk = 0; kk < 32; kk++) {
            float4 wv = *(float4*)&sh_w[kk][tx * 4];
            float  v0 = sh_a[ty * 4 + 0][kk];
            float  v1 = sh_a[ty * 4 + 1][kk];
            float  v2 = sh_a[ty * 4 + 2][kk];
            float  v3 = sh_a[ty * 4 + 3][kk];
            acc[0][0] += v0 * wv.x; acc[0][1] += v0 * wv.y; acc[0][2] += v0 * wv.z; acc[0][3] += v0 * wv.w;
            acc[1][0] += v1 * wv.x; acc[1][1] += v1 * wv.y; acc[1][2] += v1 * wv.z; acc[1][3] += v1 * wv.w;
            acc[2][0] += v2 * wv.x; acc[2][1] += v2 * wv.y; acc[2][2] += v2 * wv.z; acc[2][3] += v2 * wv.w;
            acc[3][0] += v3 * wv.x; acc[3][1] += v3 * wv.y; acc[3][2] += v3 * wv.z; acc[3][3] += v3 * wv.w;
        }
        __syncthreads();
    }

    const int jj = j0 + tx * 4;
    const float b0v = bih[(2 + d) * NH + jj + 0] + bhh[(2 + d) * NH + jj + 0];
    const float b1v = bih[(2 + d) * NH + jj + 1] + bhh[(2 + d) * NH + jj + 1];
    const float b2v = bih[(2 + d) * NH + jj + 2] + bhh[(2 + d) * NH + jj + 2];
    const float b3v = bih[(2 + d) * NH + jj + 3] + bhh[(2 + d) * NH + jj + 3];
#pragma unroll
    for (int i = 0; i < 4; i++) {
        const int m = m0 + ty * 4 + i;
        float4 r = make_float4(acc[i][0] + b0v, acc[i][1] + b1v,
                               acc[i][2] + b2v, acc[i][3] + b3v);
        *(float4*)&g_xs1[(d * NT * NB + m) * NH + jj] = r;
    }
}

// ---------------------------------------------------------------------------
// Encoder layer 1 step: h = tanh(xs1[d][t] + h_prev @ Whh1[d]^T)
// ---------------------------------------------------------------------------
__global__ void __launch_bounds__(256) enc1_step(
    const float* __restrict__ Whh1, int t)
{
    __shared__ __align__(16) float sh_h[32][36];
    __shared__ __align__(16) float sh_w[32][36];

    const int d  = blockIdx.z;
    const int td = d ? (NT - 1 - t) : t;
    const int j0 = blockIdx.x * 32;
    const int b0 = blockIdx.y * 32;
    const int tx = threadIdx.x & 7;
    const int ty = threadIdx.x >> 3;
    const int b  = b0 + ty;
    const int j  = j0 + tx * 4;

    const float* Whh   = Whh1 + d * NH * NH;
    const float* hprev = g_h[t & 1] + d * NB * NH;
    float*       hnext = g_h[(t + 1) & 1] + d * NB * NH;

    float4 xt = *(const float4*)&g_xs1[((d * NT + td) * NB + b) * NH + j];
    float a0 = xt.x, a1 = xt.y, a2 = xt.z, a3 = xt.w;

    if (t > 0) {
        const int lb = ty, lk = tx * 4;
        for (int k0 = 0; k0 < NH; k0 += 32) {
            *(float4*)&sh_h[lb][lk] = *(const float4*)&hprev[(b0 + lb) * NH + k0 + lk];
            float4 w = *(const float4*)&Whh[(j0 + lb) * NH + k0 + lk];
            sh_w[lk + 0][lb] = w.x; sh_w[lk + 1][lb] = w.y;
            sh_w[lk + 2][lb] = w.z; sh_w[lk + 3][lb] = w.w;
            __syncthreads();
#pragma unroll
            for (int kk = 0; kk < 32; kk++) {
                float  hv = sh_h[ty][kk];
                float4 wv = *(float4*)&sh_w[kk][tx * 4];
                a0 += hv * wv.x; a1 += hv * wv.y; a2 += hv * wv.z; a3 += hv * wv.w;
            }
            __syncthreads();
        }
    }

    float4 hv4 = make_float4(tanhf(a0), tanhf(a1), tanhf(a2), tanhf(a3));
    *(float4*)&hnext[b * NH + j] = hv4;
    if (t == NT - 1)
        *(float4*)&g_dech[0][((2 + d) * NB + b) * NH + j] = hv4;  // hn slots 2 (fwd), 3 (bwd)
}

// ---------------------------------------------------------------------------
// Decoder: generic layer kernel. tile 16b x 32j, 128 threads, 4 out/thread.
// ---------------------------------------------------------------------------
__device__ __forceinline__ void gemm16x32(
    const float* __restrict__ V, const float* __restrict__ W,
    int b0, int j0, int tx, int ty,
    float& a0, float& a1, float& a2, float& a3,
    float (*sh_v)[36], float (*sh_w)[36])
{
    const int lb = threadIdx.x >> 3;        // 0..15
    const int lk = (threadIdx.x & 7) * 4;   // 0..28
    for (int k0 = 0; k0 < NH; k0 += 32) {
        *(float4*)&sh_v[lb][lk] = *(const float4*)&V[(b0 + lb) * NH + k0 + lk];
        float4 w0 = *(const float4*)&W[(j0 + lb) * NH + k0 + lk];
        float4 w1 = *(const float4*)&W[(j0 + lb + 16) * NH + k0 + lk];
        sh_w[lk + 0][lb] = w0.x; sh_w[lk + 1][lb] = w0.y;
        sh_w[lk + 2][lb] = w0.z; sh_w[lk + 3][lb] = w0.w;
        sh_w[lk + 0][lb + 16] = w1.x; sh_w[lk + 1][lb + 16] = w1.y;
        sh_w[lk + 2][lb + 16] = w1.z; sh_w[lk + 3][lb + 16] = w1.w;
        __syncthreads();
#pragma unroll
        for (int kk = 0; kk < 32; kk++) {
            float  hv = sh_v[ty][kk];
            float4 wv = *(float4*)&sh_w[kk][tx * 4];
            a0 += hv * wv.x; a1 += hv * wv.y; a2 += hv * wv.z; a3 += hv * wv.w;
        }
        __syncthreads();
    }
}

__global__ void __launch_bounds__(128) dec_layer(
    const float* __restrict__ x,   const float* __restrict__ Wih0,
    const float* __restrict__ Wihr, const float* __restrict__ Whh,
    const float* __restrict__ bih, const float* __restrict__ bhh,
    int t, int l)
{
    __shared__ __align__(16) float sh_v[16][36];
    __shared__ __align__(16) float sh_w[32][36];

    const int p  = t & 1;
    const int j0 = blockIdx.x * 32;
    const int b0 = blockIdx.y * 16;
    const int tx = threadIdx.x & 7;
    const int ty = threadIdx.x >> 3;    // 0..15
    const int b  = b0 + ty;
    const int j  = j0 + tx * 4;

    float a0 = bih[l * NH + j + 0] + bhh[l * NH + j + 0];
    float a1 = bih[l * NH + j + 1] + bhh[l * NH + j + 1];
    float a2 = bih[l * NH + j + 2] + bhh[l * NH + j + 2];
    float a3 = bih[l * NH + j + 3] + bhh[l * NH + j + 3];

    if (l == 0) {
        float i0, i1, i2;
        if (t == 0) {
            const float* xr = x + (b * NT + (NT - 1)) * NIN;
            i0 = xr[0]; i1 = xr[1]; i2 = xr[2];
        } else {
            const float* dr = g_decin[p] + b * 4;
            i0 = dr[0]; i1 = dr[1]; i2 = dr[2];
        }
        const float* wi = Wih0 + j * NIN;
        a0 += i0 * wi[0] + i1 * wi[1]  + i2 * wi[2];
        a1 += i0 * wi[3] + i1 * wi[4]  + i2 * wi[5];
        a2 += i0 * wi[6] + i1 * wi[7]  + i2 * wi[8];
        a3 += i0 * wi[9] + i1 * wi[10] + i2 * wi[11];
    }

    // recurrent term (t=0 reads hn written by the encoder)
    gemm16x32(g_dech[p] + l * NB * NH, Whh + l * NH * NH,
              b0, j0, tx, ty, a0, a1, a2, a3, sh_v, sh_w);
    // input term from layer below (written earlier this step)
    if (l > 0)
        gemm16x32(g_dech[1 - p] + (l - 1) * NB * NH, Wihr + (l - 1) * NH * NH,
                  b0, j0, tx, ty, a0, a1, a2, a3, sh_v, sh_w);

    float* hout = g_dech[1 - p] + l * NB * NH;
    float4 r = make_float4(tanhf(a0), tanhf(a1), tanhf(a2), tanhf(a3));
    *(float4*)&hout[b * NH + j] = r;
}

// ---------------------------------------------------------------------------
// Decoder output + feedback: out = h3 . linW + b;  nxt = [o0, x0-o0, x1-(x0-o0)]
// 32 blocks x 128 threads, one warp per batch row.
// ---------------------------------------------------------------------------
__global__ void __launch_bounds__(128) out_step(
    const float* __restrict__ x, const float* __restrict__ linW,
    const float* __restrict__ linb, float* __restrict__ out, int t)
{
    const int p    = t & 1;
    const int warp = threadIdx.x >> 5;
    const int lane = threadIdx.x & 31;
    const int b    = blockIdx.x * 4 + warp;

    const float* h3 = g_dech[1 - p] + 3 * NB * NH + b * NH;
    float s = 0.f;
#pragma unroll
    for (int j = lane; j < NH; j += 32) s += h3[j] * linW[j];
#pragma unroll
    for (int o = 16; o; o >>= 1) s += __shfl_xor_sync(0xffffffffu, s, o);

    if (lane == 0) {
        float o0 = s + linb[0];
        float xi0, xi1;
        if (t == 0) {
            const float* xr = x + (b * NT + (NT - 1)) * NIN;
            xi0 = xr[0]; xi1 = xr[1];
        } else {
            xi0 = g_decin[p][b * 4 + 0];
            xi1 = g_decin[p][b * 4 + 1];
        }
        float s1 = xi0 - o0;
        float s2 = xi1 - s1;
        g_decin[1 - p][b * 4 + 0] = o0;
        g_decin[1 - p][b * 4 + 1] = s1;
        g_decin[1 - p][b * 4 + 2] = s2;
        out[b * NTGT + t] = o0;
    }
}

// ---------------------------------------------------------------------------
// Launch sequence (graph-capturable: kernel launches only)
// ---------------------------------------------------------------------------
extern "C" void kernel_launch(void* const* d_in, const int* in_sizes, int n_in,
                              void* d_out, int out_size)
{
    const float* x        = (const float*)d_in[0];
    // d_in[1] = y (unused: teacher_forcing_ratio == 0)
    const float* enc_Wih0 = (const float*)d_in[2];
    const float* enc_Whh0 = (const float*)d_in[3];
    const float* enc_Wih1 = (const float*)d_in[4];
    const float* enc_Whh1 = (const float*)d_in[5];
    const float* enc_bih  = (const float*)d_in[6];
    const float* enc_bhh  = (const float*)d_in[7];
    const float* dec_Wih0 = (const float*)d_in[8];
    const float* dec_Wihr = (const float*)d_in[9];
    const float* dec_Whh  = (const float*)d_in[10];
    const float* dec_bih  = (const float*)d_in[11];
    const float* dec_bhh  = (const float*)d_in[12];
    const float* lin_W    = (const float*)d_in[13];
    const float* lin_b    = (const float*)d_in[14];
    float* out = (float*)d_out;

    const dim3 encGrid(16, 4, 2);   // j-tiles, b-tiles, dirs

    // Encoder layer 0 (fwd+bwd concurrently), writes l0 concat + hn[0..1]
    for (int t = 0; t < NT; t++)
        enc0_step<<<encGrid, 256>>>(x, enc_Wih0, enc_Whh0, enc_bih, enc_bhh, t);

    // Precompute layer-1 input terms for all t (both dirs), biases folded in
    xs1_gemm<<<dim3(8, 256, 2), 256>>>(enc_Wih1, enc_bih, enc_bhh);

    // Encoder layer 1 recurrence, writes hn[2..3]
    for (int t = 0; t < NT; t++)
        enc1_step<<<encGrid, 256>>>(enc_Whh1, t);

    // Decoder: 32 steps x (4 layers + output/feedback)
    for (int t = 0; t < NTGT; t++) {
        for (int l = 0; l < 4; l++)
            dec_layer<<<dim3(16, 8), 128>>>(x, dec_Wih0, dec_Wihr, dec_Whh,
                                            dec_bih, dec_bhh, t, l);
        out_step<<<32, 128>>>(x, lin_W, lin_b, out, t);
    }
}

// round 4
// speedup vs baseline: 1.1621x; 1.1592x over previous
#include <cuda_runtime.h>

// Problem constants
constexpr int NB   = 128;   // batch
constexpr int NT   = 128;   // encoder time steps
constexpr int NIN  = 3;     // input features
constexpr int NH   = 512;   // hidden
constexpr int NTGT = 32;    // decoder steps

constexpr int ENC_CTAS = 128;          // persistent grid (<=148 SMs, 1 CTA/SM -> co-resident)
constexpr int SHW_STRIDE = 36;         // padded w row (floats), 16B-aligned, reduces store conflicts
constexpr int SHH_STRIDE = 516;        // padded h row (floats), 16B-aligned, conflict-free bcast
constexpr int SHW_FLOATS = NH * SHW_STRIDE;          // 18432
constexpr int SHH_FLOATS = 32 * SHH_STRIDE;          // 16512
constexpr int ENC_SMEM   = (SHW_FLOATS + SHH_FLOATS) * 4;  // 139776 bytes

// ---------------------------------------------------------------------------
// Static device scratch (allocation-free rule: __device__ globals)
// ---------------------------------------------------------------------------
__device__ float g_l0[NT * NB * (2 * NH)];      // encoder L0 concat outputs [t][b][1024]
__device__ float g_xs1[2 * NT * NB * NH];       // precomputed L1 input terms [d][t][b][512]
__device__ float g_h[2][2 * NB * NH];           // encoder recurrent state ping-pong
__device__ float g_dech[2][4 * NB * NH];        // decoder state ping-pong
__device__ float g_decin[2][NB * 4];            // decoder feedback input (padded to 4)
__device__ unsigned g_count;                    // grid-barrier arrival counter

__global__ void reset_count() { g_count = 0u; }

// ---------------------------------------------------------------------------
// Persistent encoder layer: all 128 time steps in ONE kernel.
// 128 CTAs = (16 j-tiles x 4 b-tiles x 2 dirs), 256 threads, tile 32b x 32j.
// Whh tile lives in smem for the whole kernel (transposed [k][j]); per step we
// reload only the 32x512 h tile (L2-coherent via __ldcg) and run a sync-free
// 512-deep FFMA loop. Grid barrier (atomic counter, monotonic target) between
// steps. layer==0: init = bias + x_t@Wih, writes g_l0. layer==1: init = xs1.
// ---------------------------------------------------------------------------
__global__ void __launch_bounds__(256) enc_persist(
    const float* __restrict__ x, const float* __restrict__ Wih0,
    const float* __restrict__ Whh_all, const float* __restrict__ bih,
    const float* __restrict__ bhh, int layer)
{
    extern __shared__ float sm[];
    float* sh_w = sm;                  // [NH][SHW_STRIDE] transposed weights
    float* sh_h = sm + SHW_FLOATS;     // [32][SHH_STRIDE] h tile

    const int blk = blockIdx.x;
    const int d   = blk >> 6;          // direction
    const int bt  = (blk >> 4) & 3;    // batch tile
    const int jt  = blk & 15;          // j tile
    const int b0  = bt * 32;
    const int j0  = jt * 32;
    const int tx  = threadIdx.x & 7;   // j group (4 j per thread)
    const int ty  = threadIdx.x >> 3;  // batch row within tile (0..31)
    const int b   = b0 + ty;
    const int j   = j0 + tx * 4;

    const float* Whh = Whh_all + d * NH * NH;

    // ---- one-time: load Whh tile transposed into smem ----
    {
        const int r  = threadIdx.x >> 3;        // 0..31 (j row)
        const int c0 = (threadIdx.x & 7) * 4;   // 0..28 (k col)
        for (int k0 = 0; k0 < NH; k0 += 32) {
            float4 w = *(const float4*)&Whh[(j0 + r) * NH + k0 + c0];
            sh_w[(k0 + c0 + 0) * SHW_STRIDE + r] = w.x;
            sh_w[(k0 + c0 + 1) * SHW_STRIDE + r] = w.y;
            sh_w[(k0 + c0 + 2) * SHW_STRIDE + r] = w.z;
            sh_w[(k0 + c0 + 3) * SHW_STRIDE + r] = w.w;
        }
    }

    // ---- per-thread constants in registers ----
    float bias0 = 0.f, bias1 = 0.f, bias2 = 0.f, bias3 = 0.f;
    float wi[12];
    if (layer == 0) {
        const int boff = d * NH + j;
        bias0 = bih[boff + 0] + bhh[boff + 0];
        bias1 = bih[boff + 1] + bhh[boff + 1];
        bias2 = bih[boff + 2] + bhh[boff + 2];
        bias3 = bih[boff + 3] + bhh[boff + 3];
        const float* wp = Wih0 + (d * NH + j) * NIN;
#pragma unroll
        for (int i = 0; i < 12; i++) wi[i] = wp[i];
    }
    __syncthreads();   // sh_w ready

    unsigned target = 0;

    for (int t = 0; t < NT; t++) {
        const int td = d ? (NT - 1 - t) : t;

        // ---- load h_prev tile (L2-coherent; skipped at t==0 since h0 == 0) ----
        if (t > 0) {
            const float* hprev = g_h[t & 1] + d * NB * NH;
            const int r  = threadIdx.x >> 3;
            const int c0 = (threadIdx.x & 7) * 4;
#pragma unroll
            for (int k0 = 0; k0 < NH; k0 += 32) {
                float4 hv = __ldcg((const float4*)&hprev[(b0 + r) * NH + k0 + c0]);
                *(float4*)&sh_h[r * SHH_STRIDE + k0 + c0] = hv;
            }
            __syncthreads();
        }

        // ---- accumulator init ----
        float a0, a1, a2, a3;
        if (layer == 0) {
            const float* xr = x + (b * NT + td) * NIN;
            const float x0 = xr[0], x1 = xr[1], x2 = xr[2];
            a0 = bias0 + x0 * wi[0] + x1 * wi[1]  + x2 * wi[2];
            a1 = bias1 + x0 * wi[3] + x1 * wi[4]  + x2 * wi[5];
            a2 = bias2 + x0 * wi[6] + x1 * wi[7]  + x2 * wi[8];
            a3 = bias3 + x0 * wi[9] + x1 * wi[10] + x2 * wi[11];
        } else {
            float4 xt = *(const float4*)&g_xs1[((d * NT + td) * NB + b) * NH + j];
            a0 = xt.x; a1 = xt.y; a2 = xt.z; a3 = xt.w;
        }

        // ---- recurrent GEMM: sync-free, weights resident ----
        if (t > 0) {
            const float* hrow = &sh_h[ty * SHH_STRIDE];
            const float* wrow = &sh_w[tx * 4];
#pragma unroll 8
            for (int kk = 0; kk < NH; kk++) {
                float  hv = hrow[kk];
                float4 wv = *(const float4*)&wrow[kk * SHW_STRIDE];
                a0 += hv * wv.x; a1 += hv * wv.y; a2 += hv * wv.z; a3 += hv * wv.w;
            }
        }

        // ---- activation + writes ----
        float4 r4 = make_float4(tanhf(a0), tanhf(a1), tanhf(a2), tanhf(a3));
        float* hnext = g_h[(t + 1) & 1] + d * NB * NH;
        *(float4*)&hnext[b * NH + j] = r4;
        if (layer == 0)
            *(float4*)&g_l0[(td * NB + b) * (2 * NH) + d * NH + j] = r4;
        if (t == NT - 1)
            *(float4*)&g_dech[0][(((layer ? 2 : 0) + d) * NB + b) * NH + j] = r4;

        // ---- grid barrier (release writes, monotonic counter) ----
        if (t < NT - 1) {
            target += ENC_CTAS;
            __threadfence();          // make this thread's STGs visible at L2
            __syncthreads();
            if (threadIdx.x == 0) {
                atomicAdd(&g_count, 1u);
                while (*(volatile unsigned*)&g_count < target) { }
            }
            __syncthreads();
        }
    }
}

// ---------------------------------------------------------------------------
// Big GEMM: xs1[d][t][b][j] = l0[t][b][:] . Wih1[d][j][:] + bih1[d][j] + bhh1[d][j]
// M = 16384 (t,b), N = 512, K = 1024. Tile 64x64, 256 threads, 4x4 per thread.
// ---------------------------------------------------------------------------
__global__ void __launch_bounds__(256) xs1_gemm(
    const float* __restrict__ Wih1, const float* __restrict__ bih,
    const float* __restrict__ bhh)
{
    __shared__ __align__(16) float sh_a[64][36];
    __shared__ __align__(16) float sh_w[32][68];

    const int d  = blockIdx.z;
    const int j0 = blockIdx.x * 64;
    const int m0 = blockIdx.y * 64;
    const int tx = threadIdx.x & 15;
    const int ty = threadIdx.x >> 4;
    const int lr = threadIdx.x >> 3;
    const int lk = (threadIdx.x & 7) * 4;

    const float* Wd = Wih1 + d * NH * (2 * NH);
    float acc[4][4] = {};

    for (int k0 = 0; k0 < 2 * NH; k0 += 32) {
        *(float4*)&sh_a[lr][lk]      = *(const float4*)&g_l0[(m0 + lr) * (2 * NH) + k0 + lk];
        *(float4*)&sh_a[lr + 32][lk] = *(const float4*)&g_l0[(m0 + lr + 32) * (2 * NH) + k0 + lk];
        float4 w0 = *(const float4*)&Wd[(j0 + lr) * (2 * NH) + k0 + lk];
        float4 w1 = *(const float4*)&Wd[(j0 + lr + 32) * (2 * NH) + k0 + lk];
        sh_w[lk + 0][lr] = w0.x; sh_w[lk + 1][lr] = w0.y;
        sh_w[lk + 2][lr] = w0.z; sh_w[lk + 3][lr] = w0.w;
        sh_w[lk + 0][lr + 32] = w1.x; sh_w[lk + 1][lr + 32] = w1.y;
        sh_w[lk + 2][lr + 32] = w1.z; sh_w[lk + 3][lr + 32] = w1.w;
        __syncthreads();
#pragma unroll
        for (int kk = 0; kk < 32; kk++) {
            float4 wv = *(float4*)&sh_w[kk][tx * 4];
            float  v0 = sh_a[ty * 4 + 0][kk];
            float  v1 = sh_a[ty * 4 + 1][kk];
            float  v2 = sh_a[ty * 4 + 2][kk];
            float  v3 = sh_a[ty * 4 + 3][kk];
            acc[0][0] += v0 * wv.x; acc[0][1] += v0 * wv.y; acc[0][2] += v0 * wv.z; acc[0][3] += v0 * wv.w;
            acc[1][0] += v1 * wv.x; acc[1][1] += v1 * wv.y; acc[1][2] += v1 * wv.z; acc[1][3] += v1 * wv.w;
            acc[2][0] += v2 * wv.x; acc[2][1] += v2 * wv.y; acc[2][2] += v2 * wv.z; acc[2][3] += v2 * wv.w;
            acc[3][0] += v3 * wv.x; acc[3][1] += v3 * wv.y; acc[3][2] += v3 * wv.z; acc[3][3] += v3 * wv.w;
        }
        __syncthreads();
    }

    const int jj = j0 + tx * 4;
    const float b0v = bih[(2 + d) * NH + jj + 0] + bhh[(2 + d) * NH + jj + 0];
    const float b1v = bih[(2 + d) * NH + jj + 1] + bhh[(2 + d) * NH + jj + 1];
    const float b2v = bih[(2 + d) * NH + jj + 2] + bhh[(2 + d) * NH + jj + 2];
    const float b3v = bih[(2 + d) * NH + jj + 3] + bhh[(2 + d) * NH + jj + 3];
#pragma unroll
    for (int i = 0; i < 4; i++) {
        const int m = m0 + ty * 4 + i;
        float4 r = make_float4(acc[i][0] + b0v, acc[i][1] + b1v,
                               acc[i][2] + b2v, acc[i][3] + b3v);
        *(float4*)&g_xs1[(d * NT * NB + m) * NH + jj] = r;
    }
}

// ---------------------------------------------------------------------------
// Decoder: generic layer kernel. tile 16b x 32j, 128 threads, 4 out/thread.
// ---------------------------------------------------------------------------
__device__ __forceinline__ void gemm16x32(
    const float* __restrict__ V, const float* __restrict__ W,
    int b0, int j0, int tx, int ty,
    float& a0, float& a1, float& a2, float& a3,
    float (*sh_v)[36], float (*sh_w)[36])
{
    const int lb = threadIdx.x >> 3;
    const int lk = (threadIdx.x & 7) * 4;
    for (int k0 = 0; k0 < NH; k0 += 32) {
        *(float4*)&sh_v[lb][lk] = *(const float4*)&V[(b0 + lb) * NH + k0 + lk];
        float4 w0 = *(const float4*)&W[(j0 + lb) * NH + k0 + lk];
        float4 w1 = *(const float4*)&W[(j0 + lb + 16) * NH + k0 + lk];
        sh_w[lk + 0][lb] = w0.x; sh_w[lk + 1][lb] = w0.y;
        sh_w[lk + 2][lb] = w0.z; sh_w[lk + 3][lb] = w0.w;
        sh_w[lk + 0][lb + 16] = w1.x; sh_w[lk + 1][lb + 16] = w1.y;
        sh_w[lk + 2][lb + 16] = w1.z; sh_w[lk + 3][lb + 16] = w1.w;
        __syncthreads();
#pragma unroll
        for (int kk = 0; kk < 32; kk++) {
            float  hv = sh_v[ty][kk];
            float4 wv = *(float4*)&sh_w[kk][tx * 4];
            a0 += hv * wv.x; a1 += hv * wv.y; a2 += hv * wv.z; a3 += hv * wv.w;
        }
        __syncthreads();
    }
}

__global__ void __launch_bounds__(128) dec_layer(
    const float* __restrict__ x,   const float* __restrict__ Wih0,
    const float* __restrict__ Wihr, const float* __restrict__ Whh,
    const float* __restrict__ bih, const float* __restrict__ bhh,
    int t, int l)
{
    __shared__ __align__(16) float sh_v[16][36];
    __shared__ __align__(16) float sh_w[32][36];

    const int p  = t & 1;
    const int j0 = blockIdx.x * 32;
    const int b0 = blockIdx.y * 16;
    const int tx = threadIdx.x & 7;
    const int ty = threadIdx.x >> 3;
    const int b  = b0 + ty;
    const int j  = j0 + tx * 4;

    float a0 = bih[l * NH + j + 0] + bhh[l * NH + j + 0];
    float a1 = bih[l * NH + j + 1] + bhh[l * NH + j + 1];
    float a2 = bih[l * NH + j + 2] + bhh[l * NH + j + 2];
    float a3 = bih[l * NH + j + 3] + bhh[l * NH + j + 3];

    if (l == 0) {
        float i0, i1, i2;
        if (t == 0) {
            const float* xr = x + (b * NT + (NT - 1)) * NIN;
            i0 = xr[0]; i1 = xr[1]; i2 = xr[2];
        } else {
            const float* dr = g_decin[p] + b * 4;
            i0 = dr[0]; i1 = dr[1]; i2 = dr[2];
        }
        const float* wi = Wih0 + j * NIN;
        a0 += i0 * wi[0] + i1 * wi[1]  + i2 * wi[2];
        a1 += i0 * wi[3] + i1 * wi[4]  + i2 * wi[5];
        a2 += i0 * wi[6] + i1 * wi[7]  + i2 * wi[8];
        a3 += i0 * wi[9] + i1 * wi[10] + i2 * wi[11];
    }

    gemm16x32(g_dech[p] + l * NB * NH, Whh + l * NH * NH,
              b0, j0, tx, ty, a0, a1, a2, a3, sh_v, sh_w);
    if (l > 0)
        gemm16x32(g_dech[1 - p] + (l - 1) * NB * NH, Wihr + (l - 1) * NH * NH,
                  b0, j0, tx, ty, a0, a1, a2, a3, sh_v, sh_w);

    float* hout = g_dech[1 - p] + l * NB * NH;
    float4 r = make_float4(tanhf(a0), tanhf(a1), tanhf(a2), tanhf(a3));
    *(float4*)&hout[b * NH + j] = r;
}

// ---------------------------------------------------------------------------
// Decoder output + feedback
// ---------------------------------------------------------------------------
__global__ void __launch_bounds__(128) out_step(
    const float* __restrict__ x, const float* __restrict__ linW,
    const float* __restrict__ linb, float* __restrict__ out, int t)
{
    const int p    = t & 1;
    const int warp = threadIdx.x >> 5;
    const int lane = threadIdx.x & 31;
    const int b    = blockIdx.x * 4 + warp;

    const float* h3 = g_dech[1 - p] + 3 * NB * NH + b * NH;
    float s = 0.f;
#pragma unroll
    for (int j = lane; j < NH; j += 32) s += h3[j] * linW[j];
#pragma unroll
    for (int o = 16; o; o >>= 1) s += __shfl_xor_sync(0xffffffffu, s, o);

    if (lane == 0) {
        float o0 = s + linb[0];
        float xi0, xi1;
        if (t == 0) {
            const float* xr = x + (b * NT + (NT - 1)) * NIN;
            xi0 = xr[0]; xi1 = xr[1];
        } else {
            xi0 = g_decin[p][b * 4 + 0];
            xi1 = g_decin[p][b * 4 + 1];
        }
        float s1 = xi0 - o0;
        float s2 = xi1 - s1;
        g_decin[1 - p][b * 4 + 0] = o0;
        g_decin[1 - p][b * 4 + 1] = s1;
        g_decin[1 - p][b * 4 + 2] = s2;
        out[b * NTGT + t] = o0;
    }
}

// ---------------------------------------------------------------------------
// Launch sequence (graph-capturable: kernel launches only)
// ---------------------------------------------------------------------------
extern "C" void kernel_launch(void* const* d_in, const int* in_sizes, int n_in,
                              void* d_out, int out_size)
{
    const float* x        = (const float*)d_in[0];
    const float* enc_Wih0 = (const float*)d_in[2];
    const float* enc_Whh0 = (const float*)d_in[3];
    const float* enc_Wih1 = (const float*)d_in[4];
    const float* enc_Whh1 = (const float*)d_in[5];
    const float* enc_bih  = (const float*)d_in[6];
    const float* enc_bhh  = (const float*)d_in[7];
    const float* dec_Wih0 = (const float*)d_in[8];
    const float* dec_Wihr = (const float*)d_in[9];
    const float* dec_Whh  = (const float*)d_in[10];
    const float* dec_bih  = (const float*)d_in[11];
    const float* dec_bhh  = (const float*)d_in[12];
    const float* lin_W    = (const float*)d_in[13];
    const float* lin_b    = (const float*)d_in[14];
    float* out = (float*)d_out;

    // allow >48KB dynamic smem for the persistent encoder (idempotent)
    cudaFuncSetAttribute(enc_persist, cudaFuncAttributeMaxDynamicSharedMemorySize,
                         ENC_SMEM);

    // Encoder layer 0: persistent, all 128 steps
    reset_count<<<1, 1>>>();
    enc_persist<<<ENC_CTAS, 256, ENC_SMEM>>>(x, enc_Wih0, enc_Whh0,
                                             enc_bih, enc_bhh, 0);

    // Layer-1 input terms for all t (both dirs), biases folded in
    xs1_gemm<<<dim3(8, 256, 2), 256>>>(enc_Wih1, enc_bih, enc_bhh);

    // Encoder layer 1: persistent
    reset_count<<<1, 1>>>();
    enc_persist<<<ENC_CTAS, 256, ENC_SMEM>>>(x, enc_Wih0, enc_Whh1,
                                             enc_bih, enc_bhh, 1);

    // Decoder: 32 steps x (4 layers + output/feedback)
    for (int t = 0; t < NTGT; t++) {
        for (int l = 0; l < 4; l++)
            dec_layer<<<dim3(16, 8), 128>>>(x, dec_Wih0, dec_Wihr, dec_Whh,
                                            dec_bih, dec_bhh, t, l);
        out_step<<<32, 128>>>(x, lin_W, lin_b, out, t);
    }
}